// round 6
// baseline (speedup 1.0000x reference)
#include <cuda_runtime.h>

#define BB   4
#define SS   2048
#define DD   10
#define VV   32000
#define ROWS (BB*SS)
#define RPB  256       // rows per logits block
#define VPB  1280      // vocab per logits block (5 warps x 256)
#define WOS  11        // padded Wo row stride in shared (floats)
#define HST  12        // padded h stride (floats) for LDS.128

// scratch (device globals — no allocation allowed)
__device__ float g_Q[ROWS*DD];
__device__ float g_K[ROWS*DD];
__device__ float g_V[ROWS*DD];
__device__ float g_O[ROWS*DD];

// packed f32x2 FMA (Blackwell FFMA2)
__device__ __forceinline__ float2 ffma2(float2 a, float2 b, float2 c) {
    float2 d;
    asm("fma.rn.f32x2 %0, %1, %2, %3;"
        : "=l"(reinterpret_cast<unsigned long long&>(d))
        : "l"(reinterpret_cast<unsigned long long&>(a)),
          "l"(reinterpret_cast<unsigned long long&>(b)),
          "l"(reinterpret_cast<unsigned long long&>(c)));
    return d;
}

// no-op: keeps the ncu -s 5 -c 1 capture slot on logits_kernel
__global__ void noop_kernel() {}

// ---------------------------------------------------------------------------
// Kernel 1: h = emb[x] + pos;  G = h @ W.T  for one of {Q,K,V} per blockIdx.y.
// ---------------------------------------------------------------------------
__global__ void __launch_bounds__(128) qkv_kernel(
    const int* __restrict__ x, const float* __restrict__ emb,
    const float* __restrict__ pos, const float* __restrict__ Wq,
    const float* __restrict__ Wk, const float* __restrict__ Wv)
{
    __shared__ float sw[DD*DD];
    const float* W = (blockIdx.y == 0) ? Wq : (blockIdx.y == 1) ? Wk : Wv;
    float*       G = (blockIdx.y == 0) ? g_Q : (blockIdx.y == 1) ? g_K : g_V;

    if (threadIdx.x < DD*DD/2)
        ((float2*)sw)[threadIdx.x] = __ldg((const float2*)W + threadIdx.x);

    int row = blockIdx.x * 128 + threadIdx.x;
    int s   = row & (SS - 1);
    int tok = x[row];

    float2 h2[5];
    const float2* ep = (const float2*)(emb + tok*DD);
    const float2* pp = (const float2*)(pos + s*DD);
#pragma unroll
    for (int e = 0; e < 5; e++) {
        float2 ee = __ldg(ep + e), qq = __ldg(pp + e);
        h2[e] = make_float2(ee.x + qq.x, ee.y + qq.y);
    }
    __syncthreads();

    float2* go = (float2*)(G + row*DD);
#pragma unroll
    for (int d = 0; d < DD; d += 2) {
        float2 s0 = make_float2(0.f, 0.f), s1 = s0;
        const float2* w0 = (const float2*)(sw + d*DD);
        const float2* w1 = (const float2*)(sw + (d+1)*DD);
#pragma unroll
        for (int e = 0; e < 5; e++) {
            s0 = ffma2(h2[e], w0[e], s0);
            s1 = ffma2(h2[e], w1[e], s1);
        }
        go[d >> 1] = make_float2(s0.x + s0.y, s1.x + s1.y);
    }
}

// ---------------------------------------------------------------------------
// Kernel 2: causal attention (unchanged, known-good). 4 rows/warp, f32x2.
// Masked entries contribute exactly 0 (== reference's exp(-1e9/sqrt(d))).
// ---------------------------------------------------------------------------
__global__ void __launch_bounds__(256) attn_kernel()
{
    int b    = blockIdx.y;
    int warp = threadIdx.x >> 5;
    int lane = threadIdx.x & 31;
    const float inv_sqrt_d = 0.3162277660168379f;
    const float* Qb = g_Q + b*SS*DD;
    const float* Kb = g_K + b*SS*DD;
    const float* Vb = g_V + b*SS*DD;

    int s0 = blockIdx.x * 32 + warp * 4;
    float2 q2[4][5], acc[4][5];
    float  l[4];
#pragma unroll
    for (int r = 0; r < 4; r++) {
        l[r] = 0.f;
        const float2* qp = (const float2*)(Qb + (s0 + r)*DD);
#pragma unroll
        for (int e = 0; e < 5; e++) {
            q2[r][e]  = __ldg(qp + e);
            acc[r][e] = make_float2(0.f, 0.f);
        }
    }
    int smax = s0 + 3;
    for (int t = lane; t <= smax; t += 32) {
        float2 k2[5], v2[5];
        const float2* kp = (const float2*)(Kb + t*DD);
        const float2* vp = (const float2*)(Vb + t*DD);
#pragma unroll
        for (int e = 0; e < 5; e++) { k2[e] = __ldg(kp + e); v2[e] = __ldg(vp + e); }
#pragma unroll
        for (int r = 0; r < 4; r++) {
            float2 s2 = make_float2(0.f, 0.f);
#pragma unroll
            for (int e = 0; e < 5; e++) s2 = ffma2(q2[r][e], k2[e], s2);
            float sc = s2.x + s2.y;
            if (t <= s0 + r) {
                float ex = __expf(sc * inv_sqrt_d);
                l[r] += ex;
                float2 e2 = make_float2(ex, ex);
#pragma unroll
                for (int e = 0; e < 5; e++) acc[r][e] = ffma2(v2[e], e2, acc[r][e]);
            }
        }
    }
#pragma unroll
    for (int off = 16; off > 0; off >>= 1) {
#pragma unroll
        for (int r = 0; r < 4; r++) {
            l[r] += __shfl_xor_sync(0xffffffffu, l[r], off);
#pragma unroll
            for (int e = 0; e < 5; e++) {
                acc[r][e].x += __shfl_xor_sync(0xffffffffu, acc[r][e].x, off);
                acc[r][e].y += __shfl_xor_sync(0xffffffffu, acc[r][e].y, off);
            }
        }
    }
#pragma unroll
    for (int r = 0; r < 4; r++) {
        float il = 1.f / l[r];
        if (lane < DD) {
            float v = (lane & 1) ? acc[r][lane >> 1].y : acc[r][lane >> 1].x;
            g_O[(b*SS + s0 + r)*DD + lane] = v * il;
        }
    }
}

// ---------------------------------------------------------------------------
// Kernel 3: logits = out @ Wo.T. Fix: the old per-lane Wo prologue issued
// 40 LDG.32/lane with 160B lane stride -> 32 sectors per warp-op (~35% of
// all L1 work). Now the block stages its 1280x10 Wo chunk DENSE (float4)
// into padded shared once, lanes pick up their 80 weights via one-time LDS.
// RPB=256 halves prologue frequency. Main loop: 3 LDS.128 + 40 FFMA2 +
// 2 dense STG.128 per (warp,row).
// ---------------------------------------------------------------------------
extern __shared__ float dynsh[];
__global__ void __launch_bounds__(160) logits_kernel(
    const float* __restrict__ Wo, float* __restrict__ out)
{
    float* swo = dynsh;                 // VPB * WOS floats
    float* shh = dynsh + VPB*WOS;       // RPB * HST floats

    int tid  = threadIdx.x;
    int warp = tid >> 5;
    int lane = tid & 31;
    int r0   = blockIdx.x * RPB;
    int vch  = blockIdx.y * VPB;

    // dense Wo chunk load -> padded shared scatter (one-time)
    const float4* g4 = reinterpret_cast<const float4*>(Wo + (size_t)vch * DD);
    for (int i = tid; i < VPB*DD/4; i += 160) {
        float4 t = __ldg(g4 + i);
        int f = i * 4;              // f%10 is even -> d <= 8, d+3 <= 11
        int v = f / 10, d = f - v * 10;
        float vals[4] = {t.x, t.y, t.z, t.w};
#pragma unroll
        for (int k = 0; k < 4; k++) {
            int vv = v, dd2 = d + k;
            if (dd2 >= 10) { vv++; dd2 -= 10; }
            swo[vv*WOS + dd2] = vals[k];
        }
    }
    // h staging (padded for LDS.128)
    for (int i = tid; i < RPB*DD; i += 160) {
        int row = i / DD, d = i - row*DD;
        shh[row*HST + d] = g_O[r0*DD + i];
    }
    __syncthreads();

    int vloc = warp * 256 + lane * 4;

    float2 w[2][2][DD];   // [chunk][pair][d] — one-time LDS pickup
#pragma unroll
    for (int c = 0; c < 2; c++)
#pragma unroll
        for (int p = 0; p < 2; p++)
#pragma unroll
            for (int d = 0; d < DD; d++) {
                int v = vloc + c*128 + 2*p;
                w[c][p][d].x = swo[(v    )*WOS + d];
                w[c][p][d].y = swo[(v + 1)*WOS + d];
            }

    int vbase = vch + vloc;
#pragma unroll 1
    for (int s = 0; s < RPB; s++) {
        const float4* hp = reinterpret_cast<const float4*>(shh + s*HST);
        float4 p0 = hp[0];
        float4 p1 = hp[1];
        float4 p2 = hp[2];
        float hv[DD] = {p0.x, p0.y, p0.z, p0.w, p1.x, p1.y, p1.z, p1.w, p2.x, p2.y};

        float2 a00 = make_float2(0.f, 0.f), a01 = a00, a10 = a00, a11 = a00;
#pragma unroll
        for (int d = 0; d < DD; d++) {
            float2 h2 = make_float2(hv[d], hv[d]);
            a00 = ffma2(w[0][0][d], h2, a00);
            a01 = ffma2(w[0][1][d], h2, a01);
            a10 = ffma2(w[1][0][d], h2, a10);
            a11 = ffma2(w[1][1][d], h2, a11);
        }
        size_t rowoff = (size_t)(r0 + s) * VV;
        __stcs(reinterpret_cast<float4*>(out + rowoff + vbase),
               make_float4(a00.x, a00.y, a01.x, a01.y));
        __stcs(reinterpret_cast<float4*>(out + rowoff + vbase + 128),
               make_float4(a10.x, a10.y, a11.x, a11.y));
    }
}

// ---------------------------------------------------------------------------
extern "C" void kernel_launch(void* const* d_in, const int* in_sizes, int n_in,
                              void* d_out, int out_size)
{
    const int*   x   = (const int*)  d_in[0];
    const float* emb = (const float*)d_in[1];
    const float* pos = (const float*)d_in[2];
    const float* Wq  = (const float*)d_in[3];
    const float* Wk  = (const float*)d_in[4];
    const float* Wv  = (const float*)d_in[5];
    const float* Wo  = (const float*)d_in[6];
    float* out = (float*)d_out;

    const int smem = (VPB*WOS + RPB*HST) * sizeof(float);   // 68608 B
    cudaFuncSetAttribute(logits_kernel,
                         cudaFuncAttributeMaxDynamicSharedMemorySize, smem);

    noop_kernel<<<1, 1>>>();   // keeps ncu capture slot on logits_kernel
    qkv_kernel<<<dim3(ROWS / 128, 3), 128>>>(x, emb, pos, Wq, Wk, Wv);
    attn_kernel<<<dim3(SS / 32, BB), 256>>>();
    logits_kernel<<<dim3(ROWS / RPB, VV / VPB), 160, smem>>>(Wo, out);
}